// round 4
// baseline (speedup 1.0000x reference)
#include <cuda_runtime.h>
#include <cuda_bf16.h>
#include <math.h>

#define BB 32
#define TT 2048
#define DD 256
#define HH 128

// Scratch: input projection xp0[t][b][h], and layer-0 hidden stream h0[t][b][h]
__device__ float g_xp0[(size_t)TT * BB * HH];
__device__ float g_h0 [(size_t)TT * BB * HH];

// tanh via MUFU.EX2 + MUFU.RCP: abs err ~1e-7, overflow-safe (e->0 => r->1)
__device__ __forceinline__ float fast_tanh(float x) {
    float ax = fabsf(x);
    float e  = __expf(-2.0f * ax);
    float r  = __fdividef(1.0f - e, 1.0f + e);
    return copysignf(r, x);
}

// ---------------------------------------------------------------------------
// Kernel A (round-1 proven): xp0[t][b][j] = x[b][t][:].W_ih0[j][:] + biases
// ---------------------------------------------------------------------------
__global__ __launch_bounds__(256) void input_proj_kernel(
    const float* __restrict__ x,
    const float* __restrict__ W_ih0,
    const float* __restrict__ b_ih0,
    const float* __restrict__ b_hh0)
{
    __shared__ float xs[BB][64];
    __shared__ float ws[64][HH];

    const int t   = blockIdx.x;
    const int tid = threadIdx.x;
    const int jg  = (tid & 31) * 4;
    const int bg  = (tid >> 5) * 4;

    float acc[4][4];
#pragma unroll
    for (int i = 0; i < 4; i++)
#pragma unroll
        for (int k = 0; k < 4; k++) acc[i][k] = 0.f;

    for (int k0 = 0; k0 < DD; k0 += 64) {
        for (int i = tid; i < BB * 16; i += 256) {
            int b  = i >> 4;
            int kk = (i & 15) * 4;
            *(float4*)&xs[b][kk] =
                *(const float4*)&x[((size_t)b * TT + t) * DD + k0 + kk];
        }
        for (int i = tid; i < HH * 16; i += 256) {
            int j  = i >> 4;
            int kk = (i & 15) * 4;
            float4 w = *(const float4*)&W_ih0[(size_t)j * DD + k0 + kk];
            ws[kk + 0][j] = w.x;
            ws[kk + 1][j] = w.y;
            ws[kk + 2][j] = w.z;
            ws[kk + 3][j] = w.w;
        }
        __syncthreads();

#pragma unroll 16
        for (int k = 0; k < 64; k++) {
            float4 wv = *(const float4*)&ws[k][jg];
            float x0 = xs[bg + 0][k];
            float x1 = xs[bg + 1][k];
            float x2 = xs[bg + 2][k];
            float x3 = xs[bg + 3][k];
            acc[0][0] += wv.x * x0; acc[0][1] += wv.y * x0;
            acc[0][2] += wv.z * x0; acc[0][3] += wv.w * x0;
            acc[1][0] += wv.x * x1; acc[1][1] += wv.y * x1;
            acc[1][2] += wv.z * x1; acc[1][3] += wv.w * x1;
            acc[2][0] += wv.x * x2; acc[2][1] += wv.y * x2;
            acc[2][2] += wv.z * x2; acc[2][3] += wv.w * x2;
            acc[3][0] += wv.x * x3; acc[3][1] += wv.y * x3;
            acc[3][2] += wv.z * x3; acc[3][3] += wv.w * x3;
        }
        __syncthreads();
    }

#pragma unroll
    for (int jj = 0; jj < 4; jj++) {
        float bias = b_ih0[jg + jj] + b_hh0[jg + jj];
#pragma unroll
        for (int bb2 = 0; bb2 < 4; bb2++) {
            g_xp0[((size_t)t * BB + (bg + bb2)) * HH + jg + jj] = acc[bb2][jj] + bias;
        }
    }
}

// ---------------------------------------------------------------------------
// Padded h layout: chunk cc (32 floats) starts at cc*40 (16B-aligned, and the
// 4 per-quad float4 reads land on banks {0-3, 8-11, 16-19, 24-27}).
// ---------------------------------------------------------------------------
#define PITCH 40

// ---------------------------------------------------------------------------
// Kernel B0: layer-0 recurrence. One CTA/batch, 512 threads, tid = j*4+c.
// ONE matvec on the serial chain, ONE barrier per step. Writes h0 stream.
// ---------------------------------------------------------------------------
__global__ void __launch_bounds__(512, 1) rec_l0_kernel(
    const float* __restrict__ W_hh0)
{
    const int bidx = blockIdx.x;
    const int tid  = threadIdx.x;
    const int j    = tid >> 2;
    const int c    = tid & 3;

    __shared__ __align__(16) float hbuf[2][4 * PITCH];

    float4 w[8];
    {
        const float4* p = (const float4*)&W_hh0[(size_t)j * HH + c * 32];
#pragma unroll
        for (int i = 0; i < 8; i++) w[i] = p[i];
    }

    const int posj = (j >> 5) * PITCH + (j & 31);

    for (int i = tid; i < 4 * PITCH; i += 512) {
        hbuf[0][i] = 0.f;
        hbuf[1][i] = 0.f;
    }
    __syncthreads();

    const float* xpb = g_xp0 + (size_t)bidx * HH + j;
    float*       h0o = g_h0 + (size_t)bidx * HH + j;

    float xpr = *xpb;
    xpb += (size_t)BB * HH;

    for (int t = 0; t < TT; t++) {
        const int p = t & 1;
        const float4* hrd = (const float4*)&hbuf[p][c * PITCH];

        float aa = 0.f, ab = 0.f;
#pragma unroll
        for (int i = 0; i < 8; i++) {
            float4 h = hrd[i];
            aa += w[i].x * h.x + w[i].y * h.y;
            ab += w[i].z * h.z + w[i].w * h.w;
        }
        float a = aa + ab;
        a += __shfl_xor_sync(0xFFFFFFFFu, a, 1);
        a += __shfl_xor_sync(0xFFFFFFFFu, a, 2);

        float h0n = fast_tanh(xpr + a);
        hbuf[1 - p][posj] = h0n;
        if (c == 0)
            h0o[(size_t)t * BB * HH] = h0n;    // stream h0 out for layer 1

        if (t + 1 < TT) {
            xpr = *xpb;
            xpb += (size_t)BB * HH;
        }
        __syncthreads();
    }
}

// ---------------------------------------------------------------------------
// Kernel B1: layer-1 recurrence. One CTA/batch, 512 threads.
// Serial chain = W_hh1 matvec only; the W_ih1@h0[t] term is data-parallel
// (h0 fully known): both accumulate into one register sum, one shuffle
// reduce, one tanh, one barrier. h0[t+1] prefetched global->smem during t.
// ---------------------------------------------------------------------------
__global__ void __launch_bounds__(512, 1) rec_l1_kernel(
    const float* __restrict__ W_ih1,
    const float* __restrict__ W_hh1,
    const float* __restrict__ b_ih1,
    const float* __restrict__ b_hh1,
    float* __restrict__ out)
{
    const int bidx = blockIdx.x;
    const int tid  = threadIdx.x;
    const int j    = tid >> 2;
    const int c    = tid & 3;

    __shared__ __align__(16) float h0s[2][4 * PITCH];
    __shared__ __align__(16) float h1s[2][4 * PITCH];

    float4 wih[8], whh[8];
    {
        const float4* p1 = (const float4*)&W_ih1[(size_t)j * HH + c * 32];
        const float4* p2 = (const float4*)&W_hh1[(size_t)j * HH + c * 32];
#pragma unroll
        for (int i = 0; i < 8; i++) { wih[i] = p1[i]; whh[i] = p2[i]; }
    }

    const int   posj  = (j >> 5) * PITCH + (j & 31);
    const float biasj = b_ih1[j] + b_hh1[j];

    for (int i = tid; i < 4 * PITCH; i += 512) {
        h1s[0][i] = 0.f;
        h1s[1][i] = 0.f;
    }
    // preload h0[0] into h0s[0]
    if (tid < 32) {
        int f = tid * 4;
        float4 v = *(const float4*)&g_h0[(size_t)bidx * HH + f];
        *(float4*)&h0s[0][(f >> 5) * PITCH + (f & 31)] = v;
    }
    __syncthreads();

    float* outb = out + (size_t)bidx * TT * HH;

    for (int t = 0; t < TT; t++) {
        const int p = t & 1;
        const float4* h0rd = (const float4*)&h0s[p][c * PITCH];
        const float4* h1rd = (const float4*)&h1s[p][c * PITCH];

        // parallel term (no serial dep) + serial term, fused accumulation
        float za = 0.f, zb = 0.f, sa = 0.f, sb = 0.f;
#pragma unroll
        for (int i = 0; i < 8; i++) {
            float4 g = h0rd[i];
            za += wih[i].x * g.x + wih[i].y * g.y;
            zb += wih[i].z * g.z + wih[i].w * g.w;
            float4 h = h1rd[i];
            sa += whh[i].x * h.x + whh[i].y * h.y;
            sb += whh[i].z * h.z + whh[i].w * h.w;
        }
        float a = (za + zb) + (sa + sb);
        a += __shfl_xor_sync(0xFFFFFFFFu, a, 1);
        a += __shfl_xor_sync(0xFFFFFFFFu, a, 2);

        float h1n = fast_tanh(a + biasj);
        h1s[1 - p][posj] = h1n;
        if (c == 0)
            outb[(size_t)t * HH + j] = h1n;

        // prefetch h0[t+1] into the other smem buffer (guard last step)
        if (tid < 32) {
            int tn = (t + 1 < TT) ? (t + 1) : t;
            int f  = tid * 4;
            float4 v = *(const float4*)&g_h0[((size_t)tn * BB + bidx) * HH + f];
            *(float4*)&h0s[1 - p][(f >> 5) * PITCH + (f & 31)] = v;
        }
        __syncthreads();
    }
}

// ---------------------------------------------------------------------------
extern "C" void kernel_launch(void* const* d_in, const int* in_sizes, int n_in,
                              void* d_out, int out_size)
{
    const float* x     = (const float*)d_in[0];
    const float* W_ih0 = (const float*)d_in[1];
    const float* W_hh0 = (const float*)d_in[2];
    const float* b_ih0 = (const float*)d_in[3];
    const float* b_hh0 = (const float*)d_in[4];
    const float* W_ih1 = (const float*)d_in[5];
    const float* W_hh1 = (const float*)d_in[6];
    const float* b_ih1 = (const float*)d_in[7];
    const float* b_hh1 = (const float*)d_in[8];
    float* out = (float*)d_out;

    input_proj_kernel<<<TT, 256>>>(x, W_ih0, b_ih0, b_hh0);
    rec_l0_kernel<<<BB, 512>>>(W_hh0);
    rec_l1_kernel<<<BB, 512>>>(W_ih1, W_hh1, b_ih1, b_hh1, out);
}

// round 6
// speedup vs baseline: 1.3179x; 1.3179x over previous
#include <cuda_runtime.h>
#include <cuda_bf16.h>
#include <math.h>

#define BB 32
#define TT 2048
#define DD 256
#define HH 128

// Scratch streams, all [t][b][h]
__device__ float g_xp0[(size_t)TT * BB * HH];   // layer-0 pre-activation (bias folded)
__device__ float g_h0 [(size_t)TT * BB * HH];   // layer-0 hidden stream
__device__ float g_yp [(size_t)TT * BB * HH];   // layer-1 input term (bias folded)

// tanh via MUFU.EX2 + MUFU.RCP: abs err ~1e-7, overflow-safe (e->0 => r->1)
__device__ __forceinline__ float fast_tanh(float x) {
    float ax = fabsf(x);
    float e  = __expf(-2.0f * ax);
    float r  = __fdividef(1.0f - e, 1.0f + e);
    return copysignf(r, x);
}

// ---------------------------------------------------------------------------
// GEMM body: out[t][b][j] = sum_k A(t)[b][k] * W[j][k] + bias_a[j] + bias_b[j]
// One block per t, 128 threads. Thread tile: 4 j (lane-distinct) x 8 b.
// Weights read as ONE lane-distinct float4 per k (512B/warp/k); x read as 8
// broadcast scalars from k-major smem -> FMA-port-bound, not crossbar-bound.
// A(t) row for batch b is at:  A + t*tstride + b*bstride
// ---------------------------------------------------------------------------
template <int K>
__device__ __forceinline__ void gemm_tbh_body(
    const float* __restrict__ A, size_t tstride, size_t bstride,
    const float* __restrict__ W,
    const float* __restrict__ bias_a, const float* __restrict__ bias_b,
    float* __restrict__ outp)
{
    __shared__ float ws[64][HH];      // [k][j]  32 KB
    __shared__ float xs[64][33];      // [k][b]  pitch 33 -> max 2-way store conflicts

    const int t    = blockIdx.x;
    const int tid  = threadIdx.x;
    const int lane = tid & 31;
    const int w    = tid >> 5;
    const int jg   = lane * 4;        // 4 consecutive outputs
    const int bg   = w * 8;           // 8 batch rows

    const float* At = A + (size_t)t * tstride;

    float acc[8][4];
#pragma unroll
    for (int i = 0; i < 8; i++)
#pragma unroll
        for (int q = 0; q < 4; q++) acc[i][q] = 0.f;

    for (int k0 = 0; k0 < K; k0 += 64) {
        // x tile, transposed to k-major
        for (int i = tid; i < BB * 16; i += 128) {
            int b  = i >> 4;
            int kk = (i & 15) * 4;
            float4 v = *(const float4*)&At[(size_t)b * bstride + k0 + kk];
            xs[kk + 0][b] = v.x; xs[kk + 1][b] = v.y;
            xs[kk + 2][b] = v.z; xs[kk + 3][b] = v.w;
        }
        // weight tile transposed: ws[k][j] = W[j][k0+k]
        for (int i = tid; i < HH * 16; i += 128) {
            int j  = i >> 4;
            int kk = (i & 15) * 4;
            float4 wv = *(const float4*)&W[(size_t)j * K + k0 + kk];
            ws[kk + 0][j] = wv.x; ws[kk + 1][j] = wv.y;
            ws[kk + 2][j] = wv.z; ws[kk + 3][j] = wv.w;
        }
        __syncthreads();

#pragma unroll 8
        for (int k = 0; k < 64; k++) {
            float4 wv = *(const float4*)&ws[k][jg];
            float xv[8];
#pragma unroll
            for (int i = 0; i < 8; i++) xv[i] = xs[k][bg + i];   // broadcast
#pragma unroll
            for (int i = 0; i < 8; i++) {
                acc[i][0] += wv.x * xv[i];
                acc[i][1] += wv.y * xv[i];
                acc[i][2] += wv.z * xv[i];
                acc[i][3] += wv.w * xv[i];
            }
        }
        __syncthreads();
    }

    float4 bias;
    bias.x = bias_a[jg + 0] + bias_b[jg + 0];
    bias.y = bias_a[jg + 1] + bias_b[jg + 1];
    bias.z = bias_a[jg + 2] + bias_b[jg + 2];
    bias.w = bias_a[jg + 3] + bias_b[jg + 3];

#pragma unroll
    for (int i = 0; i < 8; i++) {
        float4 o;
        o.x = acc[i][0] + bias.x;
        o.y = acc[i][1] + bias.y;
        o.z = acc[i][2] + bias.z;
        o.w = acc[i][3] + bias.w;
        *(float4*)&outp[((size_t)t * BB + bg + i) * HH + jg] = o;
    }
}

// ---------------------------------------------------------------------------
// Recurrence body: h[t] = tanh(Z[t][b][j] + W.h[t-1]), writes h to O.
// One CTA/batch, 512 threads, tid = j*4+c (c = 32-wide k-chunk).
// Weight-stationary (32 regs), quad-shuffle reduce, 1 barrier/step,
// 2-step-deep register prefetch of Z.
// O row for step t at:  O + bidx*o_bstride + t*o_tstride + j
// ---------------------------------------------------------------------------
#define PITCH 40

__device__ __forceinline__ void rec_body(
    const float* __restrict__ W,
    const float* __restrict__ Z,
    float* __restrict__ O,
    size_t o_bstride, size_t o_tstride)
{
    const int bidx = blockIdx.x;
    const int tid  = threadIdx.x;
    const int j    = tid >> 2;
    const int c    = tid & 3;

    __shared__ __align__(16) float hbuf[2][4 * PITCH];

    float4 w[8];
    {
        const float4* p = (const float4*)&W[(size_t)j * HH + c * 32];
#pragma unroll
        for (int i = 0; i < 8; i++) w[i] = p[i];
    }

    const int posj = (j >> 5) * PITCH + (j & 31);

    for (int i = tid; i < 4 * PITCH; i += 512) {
        hbuf[0][i] = 0.f;
        hbuf[1][i] = 0.f;
    }
    __syncthreads();

    const float* zp = Z + (size_t)bidx * HH + j;
    float*       op = O + (size_t)bidx * o_bstride + j;

    // 2-deep prefetch pipeline
    float z0 = zp[0];
    float z1 = zp[(size_t)BB * HH];
    zp += (size_t)2 * BB * HH;

    for (int t = 0; t < TT; t++) {
        const int p = t & 1;
        const float4* hrd = (const float4*)&hbuf[p][c * PITCH];

        float aa = 0.f, ab = 0.f;
#pragma unroll
        for (int i = 0; i < 8; i++) {
            float4 h = hrd[i];
            aa += w[i].x * h.x + w[i].y * h.y;
            ab += w[i].z * h.z + w[i].w * h.w;
        }
        float a = aa + ab;
        a += __shfl_xor_sync(0xFFFFFFFFu, a, 1);
        a += __shfl_xor_sync(0xFFFFFFFFu, a, 2);

        float hn = fast_tanh(z0 + a);
        hbuf[1 - p][posj] = hn;
        if (c == 0)
            op[(size_t)t * o_tstride] = hn;

        // rotate prefetch pipeline: load z[t+2]
        z0 = z1;
        if (t + 2 < TT) {
            z1 = *zp;
            zp += (size_t)BB * HH;
        }
        __syncthreads();
    }
}

// ---------------------------------------------------------------------------
// Thin wrappers binding the device scratch symbols (no host symbol queries).
// ---------------------------------------------------------------------------
__global__ __launch_bounds__(128) void gemm0_kernel(
    const float* __restrict__ x,
    const float* __restrict__ W_ih0,
    const float* __restrict__ b_ih0,
    const float* __restrict__ b_hh0)
{
    // xp0[t][b][j] = x[b][t][:].W_ih0[j][:] + b_ih0[j] + b_hh0[j]
    gemm_tbh_body<DD>(x, (size_t)DD, (size_t)TT * DD, W_ih0, b_ih0, b_hh0, g_xp0);
}

__global__ void __launch_bounds__(512, 1) rec0_kernel(
    const float* __restrict__ W_hh0)
{
    // h0[t][b][j] = tanh(xp0 + W_hh0.h0[t-1])
    rec_body(W_hh0, g_xp0, g_h0, (size_t)HH, (size_t)BB * HH);
}

__global__ __launch_bounds__(128) void gemm1_kernel(
    const float* __restrict__ W_ih1,
    const float* __restrict__ b_ih1,
    const float* __restrict__ b_hh1)
{
    // yp[t][b][j] = h0[t][b][:].W_ih1[j][:] + b_ih1[j] + b_hh1[j]
    gemm_tbh_body<HH>(g_h0, (size_t)BB * HH, (size_t)HH, W_ih1, b_ih1, b_hh1, g_yp);
}

__global__ void __launch_bounds__(512, 1) rec1_kernel(
    const float* __restrict__ W_hh1,
    float* __restrict__ out)
{
    // out[b][t][j] = h1[t] = tanh(yp + W_hh1.h1[t-1])
    rec_body(W_hh1, g_yp, out, (size_t)TT * HH, (size_t)HH);
}

// ---------------------------------------------------------------------------
extern "C" void kernel_launch(void* const* d_in, const int* in_sizes, int n_in,
                              void* d_out, int out_size)
{
    const float* x     = (const float*)d_in[0];
    const float* W_ih0 = (const float*)d_in[1];
    const float* W_hh0 = (const float*)d_in[2];
    const float* b_ih0 = (const float*)d_in[3];
    const float* b_hh0 = (const float*)d_in[4];
    const float* W_ih1 = (const float*)d_in[5];
    const float* W_hh1 = (const float*)d_in[6];
    const float* b_ih1 = (const float*)d_in[7];
    const float* b_hh1 = (const float*)d_in[8];
    float* out = (float*)d_out;

    gemm0_kernel<<<TT, 128>>>(x, W_ih0, b_ih0, b_hh0);
    rec0_kernel<<<BB, 512>>>(W_hh0);
    gemm1_kernel<<<TT, 128>>>(W_ih1, b_ih1, b_hh1);
    rec1_kernel<<<BB, 512>>>(W_hh1, out);
}